// round 9
// baseline (speedup 1.0000x reference)
#include <cuda_runtime.h>
#include <math.h>

#define NTOK 16384
#define DDIM 2048
#define NEXP 64
#define TOPK 8

// output layout (floats)
#define OFF_TOP   0            // 16384*8
#define OFF_SC    131072       // 16384*64
#define OFF_IDX   1179648      // 16384*8
#define OFF_HIST  1310720      // 64
#define OFF_ENT   1310784      // 1

#define BM 64
#define BK 16
#define SSTR 68                 // padded row stride (floats), 16B-aligned
#define NT (DDIM / BK)          // 128 k-tiles

typedef unsigned long long u64;

__device__ __forceinline__ u64 dup2(float v) {
    u64 r; asm("mov.b64 %0, {%1, %1};" : "=l"(r) : "f"(v)); return r;
}
__device__ __forceinline__ void ffma2(u64& d, u64 a, u64 b) {
    asm("fma.rn.f32x2 %0, %1, %2, %0;" : "+l"(d) : "l"(a), "l"(b));
}

union F4U { float4 f; u64 u[2]; };
union U64F2 { u64 u; float2 f; };

__global__ void zero_tail_kernel(float* out) {
    int i = threadIdx.x;
    if (i < 65) out[OFF_HIST + i] = 0.0f;
}

__global__ __launch_bounds__(128, 4)
void router_kernel(const float* __restrict__ x,
                   const float* __restrict__ W,
                   const float* __restrict__ bias,
                   float* __restrict__ out)
{
    __shared__ float As[2][BK][SSTR];   // [buf][k][m]
    __shared__ float Bs[2][BK][SSTR];   // [buf][k][n]
    __shared__ float Sc[64 * 65];       // scores tile [m][e]
    __shared__ float sbias[64];
    __shared__ float shist[64];

    const int tid = threadIdx.x;
    const int tm4 = (tid & 15) * 4;     // 4 consecutive m per thread
    const int n0  = (tid >> 4) * 8;     // 8 consecutive n per thread
    const int m0  = blockIdx.x * BM;

    if (tid < 64) { sbias[tid] = bias[tid]; shist[tid] = 0.0f; }

    // accumulators: acc[p][j] = f32x2 over m-pair (tm4+2p, tm4+2p+1), n = n0+j
    u64 acc[2][8];
#pragma unroll
    for (int p = 0; p < 2; p++)
#pragma unroll
        for (int j = 0; j < 8; j++) acc[p][j] = 0ULL;

    // staging loads: each thread fetches 8 x-floats and 8 W-floats per tile
    const int lrow = tid >> 1;          // 0..63
    const int lk   = (tid & 1) * 8;     // 0 or 8
    const float* xp = x + (size_t)(m0 + lrow) * DDIM + lk;
    const float* wp = W + (size_t)lrow * DDIM + lk;

    float4 xa = *(const float4*)(xp);
    float4 xb = *(const float4*)(xp + 4);
    float4 wa = *(const float4*)(wp);
    float4 wb = *(const float4*)(wp + 4);

    for (int t = 0; t < NT; t++) {
        const int buf = t & 1;
        // store staged tile (transposed to [k][m] / [k][n])
        As[buf][lk + 0][lrow] = xa.x;  As[buf][lk + 1][lrow] = xa.y;
        As[buf][lk + 2][lrow] = xa.z;  As[buf][lk + 3][lrow] = xa.w;
        As[buf][lk + 4][lrow] = xb.x;  As[buf][lk + 5][lrow] = xb.y;
        As[buf][lk + 6][lrow] = xb.z;  As[buf][lk + 7][lrow] = xb.w;
        Bs[buf][lk + 0][lrow] = wa.x;  Bs[buf][lk + 1][lrow] = wa.y;
        Bs[buf][lk + 2][lrow] = wa.z;  Bs[buf][lk + 3][lrow] = wa.w;
        Bs[buf][lk + 4][lrow] = wb.x;  Bs[buf][lk + 5][lrow] = wb.y;
        Bs[buf][lk + 6][lrow] = wb.z;  Bs[buf][lk + 7][lrow] = wb.w;
        __syncthreads();

        if (t + 1 < NT) {               // prefetch next tile into registers
            xp += BK; wp += BK;
            xa = *(const float4*)(xp);
            xb = *(const float4*)(xp + 4);
            wa = *(const float4*)(wp);
            wb = *(const float4*)(wp + 4);
        }

#pragma unroll
        for (int kk = 0; kk < BK; kk++) {
            F4U a;  a.f  = *(const float4*)&As[buf][kk][tm4];   // 2 m-pairs, packed
            float4 b0 = *(const float4*)&Bs[buf][kk][n0];
            float4 b1 = *(const float4*)&Bs[buf][kk][n0 + 4];
            u64 bd[8];
            bd[0] = dup2(b0.x); bd[1] = dup2(b0.y); bd[2] = dup2(b0.z); bd[3] = dup2(b0.w);
            bd[4] = dup2(b1.x); bd[5] = dup2(b1.y); bd[6] = dup2(b1.z); bd[7] = dup2(b1.w);
#pragma unroll
            for (int j = 0; j < 8; j++) {
                ffma2(acc[0][j], a.u[0], bd[j]);
                ffma2(acc[1][j], a.u[1], bd[j]);
            }
        }
        // single sync per iter: next STS targets the other buffer; the sync
        // after that STS orders it against this iteration's reads.
    }
    __syncthreads();

    // sigmoid -> smem tile + global scores
    float* scores_out = out + OFF_SC;
#pragma unroll
    for (int p = 0; p < 2; p++) {
#pragma unroll
        for (int h = 0; h < 2; h++) {
            const int m = tm4 + 2 * p + h;
            float r[8];
#pragma unroll
            for (int j = 0; j < 8; j++) {
                U64F2 v; v.u = acc[p][j];
                float lg = h ? v.f.y : v.f.x;
                r[j] = 1.0f / (1.0f + expf(-lg));
                Sc[m * 65 + n0 + j] = r[j];
            }
            float4 o0 = make_float4(r[0], r[1], r[2], r[3]);
            float4 o1 = make_float4(r[4], r[5], r[6], r[7]);
            *(float4*)&scores_out[(size_t)(m0 + m) * NEXP + n0]     = o0;
            *(float4*)&scores_out[(size_t)(m0 + m) * NEXP + n0 + 4] = o1;
        }
    }
    __syncthreads();

    // per-token top-8 (threads 0..63), strict > scan => lowest index wins ties
    if (tid < 64) {
        const int tok = m0 + tid;
        const float* row = &Sc[tid * 65];
        unsigned long long used = 0ULL;
        float ps[TOPK];
        int   pidx[TOPK];
        float ssum = 0.0f;
#pragma unroll
        for (int k = 0; k < TOPK; k++) {
            float best = -INFINITY;
            int bi = 0;
            for (int e = 0; e < NEXP; e++) {
                if ((used >> e) & 1ULL) continue;
                float v = row[e] + sbias[e];
                if (v > best) { best = v; bi = e; }
            }
            used |= (1ULL << bi);
            float s = row[bi];
            ps[k] = s; pidx[k] = bi; ssum += s;
            atomicAdd(&shist[bi], 1.0f);
        }
        float inv = 1.0f / (ssum + 1e-20f);
        float ent = 0.0f;
#pragma unroll
        for (int k = 0; k < TOPK; k++) {
            float p = ps[k] * inv;                    // ROUTE_SCALE == 1.0
            out[OFF_TOP + (size_t)tok * TOPK + k] = p;
            out[OFF_IDX + (size_t)tok * TOPK + k] = (float)pidx[k];
            ent += p * logf(p);
        }
        atomicAdd(&out[OFF_ENT], -ent * (1.0f / (float)NTOK));
    }
    __syncthreads();
    if (tid < 64) {
        float h = shist[tid];
        if (h != 0.0f) atomicAdd(&out[OFF_HIST + tid], h);
    }
}

extern "C" void kernel_launch(void* const* d_in, const int* in_sizes, int n_in,
                              void* d_out, int out_size) {
    const float* x    = (const float*)d_in[0];
    const float* W    = (const float*)d_in[1];
    const float* bias = (const float*)d_in[2];
    float* out = (float*)d_out;

    zero_tail_kernel<<<1, 96>>>(out);
    router_kernel<<<NTOK / BM, 128>>>(x, W, bias, out);
}

// round 12
// speedup vs baseline: 1.4129x; 1.4129x over previous
#include <cuda_runtime.h>
#include <cuda_bf16.h>
#include <math.h>
#include <stdint.h>

#define NTOK 16384
#define DDIM 2048
#define NEXP 64
#define TOPK 8

// output layout (floats)
#define OFF_TOP   0            // 16384*8
#define OFF_SC    131072       // 16384*64
#define OFF_IDX   1179648      // 16384*8
#define OFF_HIST  1310720      // 64
#define OFF_ENT   1310784      // 1

#define BM 64                  // tokens per CTA
#define BK 32                  // k per tile
#define NT (DDIM / BK)         // 64 iterations
#define THREADS 128

// smem: A[2][3][64 rows][80B]  then  B[2][3][64 rows][80B]
#define ROWB       80          // padded row stride in bytes (40 bf16)
#define TERM_BYTES (64 * ROWB) // 5120
#define BUF_BYTES  (3 * TERM_BYTES)
#define BREGION    (2 * BUF_BYTES)
#define DSMEM_BYTES (4 * BUF_BYTES + 128)

// pre-split gate weights: [term][expert][k] bf16
__device__ __align__(16) __nv_bfloat16 g_wb[3 * NEXP * DDIM];

// ---------------- helpers ----------------
__device__ __forceinline__ uint32_t smem_u32(const void* p) {
    uint32_t a;
    asm("{ .reg .u64 t; cvta.to.shared.u64 t, %1; cvt.u32.u64 %0, t; }" : "=r"(a) : "l"(p));
    return a;
}
__device__ __forceinline__ void cp_async16(uint32_t dst, const void* src) {
    asm volatile("cp.async.cg.shared.global [%0], [%1], 16;" :: "r"(dst), "l"(src) : "memory");
}
// exact 3-term bf16 split of a float pair -> 3 packed bf16x2 (lo=a, hi=b)
__device__ __forceinline__ void split2(float a, float b,
                                       uint32_t& p0, uint32_t& p1, uint32_t& p2) {
    asm("cvt.rn.bf16x2.f32 %0, %1, %2;" : "=r"(p0) : "f"(b), "f"(a));
    float a0 = __uint_as_float(p0 << 16);
    float b0 = __uint_as_float(p0 & 0xFFFF0000u);
    float ra = a - a0, rb = b - b0;
    asm("cvt.rn.bf16x2.f32 %0, %1, %2;" : "=r"(p1) : "f"(rb), "f"(ra));
    float a1 = __uint_as_float(p1 << 16);
    float b1 = __uint_as_float(p1 & 0xFFFF0000u);
    ra -= a1; rb -= b1;
    asm("cvt.rn.bf16x2.f32 %0, %1, %2;" : "=r"(p2) : "f"(rb), "f"(ra));
}
__device__ __forceinline__ void ldsm4(uint32_t* r, uint32_t addr) {
    asm volatile("ldmatrix.sync.aligned.m8n8.x4.shared.b16 {%0,%1,%2,%3}, [%4];"
                 : "=r"(r[0]), "=r"(r[1]), "=r"(r[2]), "=r"(r[3]) : "r"(addr));
}
__device__ __forceinline__ void mma16816(float* c, const uint32_t* a, const uint32_t* b) {
    asm volatile(
        "mma.sync.aligned.m16n8k16.row.col.f32.bf16.bf16.f32 "
        "{%0,%1,%2,%3}, {%4,%5,%6,%7}, {%8,%9}, {%0,%1,%2,%3};"
        : "+f"(c[0]), "+f"(c[1]), "+f"(c[2]), "+f"(c[3])
        : "r"(a[0]), "r"(a[1]), "r"(a[2]), "r"(a[3]), "r"(b[0]), "r"(b[1]));
}

// ---------------- pre-kernels ----------------
__global__ void zero_tail_kernel(float* out) {
    int i = threadIdx.x;
    if (i < 65) out[OFF_HIST + i] = 0.0f;
}

__global__ void wconv_kernel(const float* __restrict__ W) {
    int e = blockIdx.x;
    int k = threadIdx.x * 8;
    const float* src = W + (size_t)e * DDIM + k;
    float4 v0 = *(const float4*)(src);
    float4 v1 = *(const float4*)(src + 4);
    uint32_t t0[4], t1[4], t2[4];
    split2(v0.x, v0.y, t0[0], t1[0], t2[0]);
    split2(v0.z, v0.w, t0[1], t1[1], t2[1]);
    split2(v1.x, v1.y, t0[2], t1[2], t2[2]);
    split2(v1.z, v1.w, t0[3], t1[3], t2[3]);
    uint32_t* wb = (uint32_t*)g_wb;
    size_t base = ((size_t)e * DDIM + k) >> 1;
    size_t tstr = ((size_t)NEXP * DDIM) >> 1;
    *(uint4*)(wb + base)            = make_uint4(t0[0], t0[1], t0[2], t0[3]);
    *(uint4*)(wb + base + tstr)     = make_uint4(t1[0], t1[1], t1[2], t1[3]);
    *(uint4*)(wb + base + 2 * tstr) = make_uint4(t2[0], t2[1], t2[2], t2[3]);
}

// ---------------- main kernel ----------------
__global__ __launch_bounds__(THREADS, 2)
void router_mma_kernel(const float* __restrict__ x,
                       const float* __restrict__ bias,
                       float* __restrict__ out)
{
    extern __shared__ char dsm[];
    __shared__ float sbias[NEXP];
    __shared__ float shist[NEXP];

    const int tid  = threadIdx.x;
    const int lane = tid & 31;
    const int w    = tid >> 5;
    const int m0   = blockIdx.x * BM;

    const uint32_t SA = (smem_u32(dsm) + 127) & ~127u;
    #define AOFF(buf, term) (SA + (buf) * BUF_BYTES + (term) * TERM_BYTES)
    #define BOFF(buf, term) (SA + BREGION + (buf) * BUF_BYTES + (term) * TERM_BYTES)

    if (tid < NEXP) { sbias[tid] = bias[tid]; shist[tid] = 0.0f; }

    // warp tile: 32m x 32n
    const int wm0 = (w >> 1) * 32;
    const int wn0 = (w & 1) * 32;

    // ldmatrix per-lane address components
    const int lj = lane >> 3, li = lane & 7;
    const int arow_l = (lj & 1) * 8 + li;
    const int akb    = (lj >> 1) * 16;
    const int brow_l = (lj >> 1) * 8 + li;
    const int bkb    = (lj & 1) * 16;

    // accM: main (0,0) product, current chunk; accT: flushed total; accC: corrections
    float accM[2][4][4], accT[2][4][4], accC[2][4][4];
#pragma unroll
    for (int mt = 0; mt < 2; mt++)
#pragma unroll
        for (int nt = 0; nt < 4; nt++)
#pragma unroll
            for (int r = 0; r < 4; r++) {
                accM[mt][nt][r] = 0.0f; accT[mt][nt][r] = 0.0f; accC[mt][nt][r] = 0.0f;
            }

    // x staging: each thread handles 16 floats: row = tid>>1, koff = (tid&1)*16
    const int xrow  = tid >> 1;
    const int xkoff = (tid & 1) * 16;
    const float* xptr = x + (size_t)(m0 + xrow) * DDIM + xkoff;
    const uint32_t a_sts = xrow * ROWB + xkoff * 2;

    float4 xr[4];
#pragma unroll
    for (int j = 0; j < 4; j++) xr[j] = *(const float4*)(xptr + j * 4);

    auto split_store = [&](int buf) {
        uint32_t s0[8], s1[8], s2[8];
#pragma unroll
        for (int j = 0; j < 4; j++) {
            split2(xr[j].x, xr[j].y, s0[2*j],   s1[2*j],   s2[2*j]);
            split2(xr[j].z, xr[j].w, s0[2*j+1], s1[2*j+1], s2[2*j+1]);
        }
        uint32_t d0 = AOFF(buf, 0) + a_sts, d1 = AOFF(buf, 1) + a_sts, d2 = AOFF(buf, 2) + a_sts;
        asm volatile("st.shared.v4.b32 [%0], {%1,%2,%3,%4};" :: "r"(d0),      "r"(s0[0]), "r"(s0[1]), "r"(s0[2]), "r"(s0[3]) : "memory");
        asm volatile("st.shared.v4.b32 [%0], {%1,%2,%3,%4};" :: "r"(d0 + 16), "r"(s0[4]), "r"(s0[5]), "r"(s0[6]), "r"(s0[7]) : "memory");
        asm volatile("st.shared.v4.b32 [%0], {%1,%2,%3,%4};" :: "r"(d1),      "r"(s1[0]), "r"(s1[1]), "r"(s1[2]), "r"(s1[3]) : "memory");
        asm volatile("st.shared.v4.b32 [%0], {%1,%2,%3,%4};" :: "r"(d1 + 16), "r"(s1[4]), "r"(s1[5]), "r"(s1[6]), "r"(s1[7]) : "memory");
        asm volatile("st.shared.v4.b32 [%0], {%1,%2,%3,%4};" :: "r"(d2),      "r"(s2[0]), "r"(s2[1]), "r"(s2[2]), "r"(s2[3]) : "memory");
        asm volatile("st.shared.v4.b32 [%0], {%1,%2,%3,%4};" :: "r"(d2 + 16), "r"(s2[4]), "r"(s2[5]), "r"(s2[6]), "r"(s2[7]) : "memory");
    };

    auto b_copy = [&](int buf, int t) {
#pragma unroll
        for (int i = 0; i < 6; i++) {
            int idx  = tid + i * 128;
            int term = idx >> 8;
            int e    = (idx >> 2) & 63;
            int q    = idx & 3;
            uint32_t dst = BOFF(buf, term) + e * ROWB + q * 16;
            const __nv_bfloat16* src = g_wb + ((size_t)term * NEXP + e) * DDIM + t * BK + q * 8;
            cp_async16(dst, src);
        }
        asm volatile("cp.async.commit_group;" ::: "memory");
    };

    // prologue: tile 0
    split_store(0);
    b_copy(0, 0);
    xr[0] = *(const float4*)(xptr + BK);
    xr[1] = *(const float4*)(xptr + BK + 4);
    xr[2] = *(const float4*)(xptr + BK + 8);
    xr[3] = *(const float4*)(xptr + BK + 12);

#pragma unroll 1
    for (int t = 0; t < NT; t++) {
        const int buf = t & 1;
        if (t + 1 < NT) {
            split_store(buf ^ 1);
            b_copy(buf ^ 1, t + 1);
            asm volatile("cp.async.wait_group 1;" ::: "memory");
        } else {
            asm volatile("cp.async.wait_group 0;" ::: "memory");
        }
        __syncthreads();

        if (t + 2 < NT) {
            const float* nx = xptr + (t + 2) * BK;
            xr[0] = *(const float4*)(nx);
            xr[1] = *(const float4*)(nx + 4);
            xr[2] = *(const float4*)(nx + 8);
            xr[3] = *(const float4*)(nx + 12);
        }

#pragma unroll
        for (int kk = 0; kk < 2; kk++) {
            // term 0 fragments -> main product into accM
            uint32_t a0[2][4], b0[2][4];
#pragma unroll
            for (int mt = 0; mt < 2; mt++)
                ldsm4(a0[mt], AOFF(buf, 0) + (wm0 + mt * 16 + arow_l) * ROWB + kk * 32 + akb);
#pragma unroll
            for (int h = 0; h < 2; h++)
                ldsm4(b0[h], BOFF(buf, 0) + (wn0 + h * 16 + brow_l) * ROWB + kk * 32 + bkb);
#pragma unroll
            for (int mt = 0; mt < 2; mt++)
#pragma unroll
                for (int nt = 0; nt < 4; nt++)
                    mma16816(accM[mt][nt], a0[mt], &b0[nt >> 1][(nt & 1) * 2]);

            // term 1 fragments -> corrections (0,1),(1,0),(1,1) into accC
            uint32_t a1[2][4], b1[2][4];
#pragma unroll
            for (int mt = 0; mt < 2; mt++)
                ldsm4(a1[mt], AOFF(buf, 1) + (wm0 + mt * 16 + arow_l) * ROWB + kk * 32 + akb);
#pragma unroll
            for (int h = 0; h < 2; h++)
                ldsm4(b1[h], BOFF(buf, 1) + (wn0 + h * 16 + brow_l) * ROWB + kk * 32 + bkb);
#pragma unroll
            for (int mt = 0; mt < 2; mt++)
#pragma unroll
                for (int nt = 0; nt < 4; nt++) {
                    mma16816(accC[mt][nt], a0[mt], &b1[nt >> 1][(nt & 1) * 2]);
                    mma16816(accC[mt][nt], a1[mt], &b0[nt >> 1][(nt & 1) * 2]);
                    mma16816(accC[mt][nt], a1[mt], &b1[nt >> 1][(nt & 1) * 2]);
                }

            // term 2 fragments -> corrections (0,2),(2,0) into accC
            uint32_t a2[2][4], b2[2][4];
#pragma unroll
            for (int mt = 0; mt < 2; mt++)
                ldsm4(a2[mt], AOFF(buf, 2) + (wm0 + mt * 16 + arow_l) * ROWB + kk * 32 + akb);
#pragma unroll
            for (int h = 0; h < 2; h++)
                ldsm4(b2[h], BOFF(buf, 2) + (wn0 + h * 16 + brow_l) * ROWB + kk * 32 + bkb);
#pragma unroll
            for (int mt = 0; mt < 2; mt++)
#pragma unroll
                for (int nt = 0; nt < 4; nt++) {
                    mma16816(accC[mt][nt], a0[mt], &b2[nt >> 1][(nt & 1) * 2]);
                    mma16816(accC[mt][nt], a2[mt], &b0[nt >> 1][(nt & 1) * 2]);
                }
        }

        // chunk flush: keeps the main-term rounding walk short (32 MMAs/chunk)
        if ((t & 15) == 15) {
#pragma unroll
            for (int mt = 0; mt < 2; mt++)
#pragma unroll
                for (int nt = 0; nt < 4; nt++)
#pragma unroll
                    for (int r = 0; r < 4; r++) {
                        accT[mt][nt][r] += accM[mt][nt][r];
                        accM[mt][nt][r] = 0.0f;
                    }
        }
        __syncthreads();
    }

    // ---------------- epilogue ----------------
    float* ScA = (float*)(dsm + (SA - smem_u32(dsm)));   // reuse tile smem
#pragma unroll
    for (int mt = 0; mt < 2; mt++)
#pragma unroll
        for (int nt = 0; nt < 4; nt++)
#pragma unroll
            for (int h = 0; h < 2; h++) {
                int m = wm0 + mt * 16 + h * 8 + (lane >> 2);
                int n = wn0 + nt * 8 + (lane & 3) * 2;
                float l0 = accT[mt][nt][2*h]   + accC[mt][nt][2*h];
                float l1 = accT[mt][nt][2*h+1] + accC[mt][nt][2*h+1];
                float v0 = 1.0f / (1.0f + expf(-l0));
                float v1 = 1.0f / (1.0f + expf(-l1));
                ScA[m * 65 + n]     = v0;
                ScA[m * 65 + n + 1] = v1;
                *(float2*)&out[OFF_SC + (size_t)(m0 + m) * NEXP + n] = make_float2(v0, v1);
            }
    __syncthreads();

    // per-token top-8 (threads 0..63), strict > scan => lowest index wins ties
    if (tid < 64) {
        const int tok = m0 + tid;
        const float* row = &ScA[tid * 65];
        unsigned long long used = 0ULL;
        float ps[TOPK]; int pidx[TOPK];
        float ssum = 0.0f;
        for (int k = 0; k < TOPK; k++) {
            float best = -INFINITY, bsc = 0.0f;
            int bi = 0;
#pragma unroll
            for (int e = 0; e < NEXP; e++) {
                float v = row[e] + sbias[e];
                if (!((used >> e) & 1ULL) && v > best) { best = v; bi = e; bsc = row[e]; }
            }
            used |= (1ULL << bi);
            ps[k] = bsc; pidx[k] = bi; ssum += bsc;
            atomicAdd(&shist[bi], 1.0f);
        }
        float inv = 1.0f / (ssum + 1e-20f);
        float ent = 0.0f;
#pragma unroll
        for (int k = 0; k < TOPK; k++) {
            float p = ps[k] * inv;             // ROUTE_SCALE == 1.0
            out[OFF_TOP + (size_t)tok * TOPK + k] = p;
            out[OFF_IDX + (size_t)tok * TOPK + k] = (float)pidx[k];
            ent += p * logf(p);
        }
        atomicAdd(&out[OFF_ENT], -ent * (1.0f / (float)NTOK));
    }
    __syncthreads();
    if (tid < NEXP) {
        float h = shist[tid];
        if (h != 0.0f) atomicAdd(&out[OFF_HIST + tid], h);
    }
}

extern "C" void kernel_launch(void* const* d_in, const int* in_sizes, int n_in,
                              void* d_out, int out_size) {
    const float* x    = (const float*)d_in[0];
    const float* W    = (const float*)d_in[1];
    const float* bias = (const float*)d_in[2];
    float* out = (float*)d_out;

    cudaFuncSetAttribute(router_mma_kernel,
                         cudaFuncAttributeMaxDynamicSharedMemorySize, DSMEM_BYTES);
    zero_tail_kernel<<<1, 96>>>(out);
    wconv_kernel<<<NEXP, 256>>>(W);
    router_mma_kernel<<<NTOK / BM, THREADS, DSMEM_BYTES>>>(x, bias, out);
}